// round 1
// baseline (speedup 1.0000x reference)
#include <cuda_runtime.h>
#include <math.h>

#define NH   200   // hidden neurons
#define BR   8     // branches
#define IND  120   // input dim (3*40)
#define OD   35    // outputs
#define TT   250   // timesteps
#define PER  15    // inputs per branch
#define W2STRIDE 201  // padded (odd) row stride for conflict-free smem reads

__device__ __forceinline__ float sigm(float v) { return 1.0f / (1.0f + expf(-v)); }

__global__ __launch_bounds__(256, 1)
void snn_fused_kernel(const float* __restrict__ x,
                      const float* __restrict__ W1,
                      const float* __restrict__ b1,
                      const float* __restrict__ tau_m1,
                      const float* __restrict__ tau_n1,
                      const float* __restrict__ W2,
                      const float* __restrict__ b2,
                      const float* __restrict__ tau_m2,
                      float* __restrict__ out)
{
    __shared__ float xsbuf[2][128];        // branch-padded xt, double buffered
    __shared__ float spkS[NH];             // spikes this step
    __shared__ float W2s[OD * W2STRIDE];   // readout weights, padded rows
    __shared__ float psum[7 * OD];         // readout partial sums
    __shared__ float accS[OD];             // final accumulator for log_softmax

    const int tid = threadIdx.x;
    const int b   = blockIdx.x;

    // ---- load W2 into smem (stride-padded) ----
    for (int idx = tid; idx < OD * NH; idx += blockDim.x) {
        int o  = idx / NH;
        int nn = idx - o * NH;
        W2s[o * W2STRIDE + nn] = W2[idx];
    }
    // ---- zero the slot-15 pads of both xs buffers (written once, never touched again) ----
    if (tid < 16) {
        int buf = tid >> 3, k = tid & 7;
        xsbuf[buf][k * 16 + 15] = 0.0f;
    }

    // ---- per-neuron state (threads 0..199) ----
    float w[128];          // 8 branches x 16 slots (slot 15 = 0)
    float beta[BR];
    float dstate[BR];
    float alpha1 = 0.0f, bb1 = 0.0f, mem1 = 0.0f, spk = 0.0f;

    if (tid < NH) {
        const int n = tid;
        #pragma unroll
        for (int k = 0; k < BR; k++) {
            const float* src = W1 + (size_t)n * (BR * IND) + k * IND + k * PER;
            #pragma unroll
            for (int j = 0; j < PER; j++) w[k * 16 + j] = src[j];
            w[k * 16 + 15] = 0.0f;
            beta[k]   = sigm(tau_n1[n * BR + k]);
            dstate[k] = 0.0f;
        }
        alpha1 = sigm(tau_m1[tid]);
        bb1    = b1[tid];
    } else {
        #pragma unroll
        for (int k = 0; k < BR; k++) { beta[k] = 0.0f; dstate[k] = 0.0f; }
        #pragma unroll
        for (int p = 0; p < 128; p++) w[p] = 0.0f;
    }

    // ---- readout-owner state (threads 0..34 own output o = tid) ----
    float alpha2 = 0.0f, bb2 = 0.0f, mem2 = 0.0f, racc = 0.0f;
    if (tid < OD) {
        alpha2 = sigm(tau_m2[tid]);
        bb2    = b2[tid];
    }

    // ---- readout slice mapping: tid = s*35 + o, s in [0,7), each slice ~29 neurons ----
    const int s_slice = tid / OD;            // 0..6 for tid<245
    const int o_slice = tid - s_slice * OD;  // 0..34
    const int rn0 = s_slice * 29;
    const int rn1 = (rn0 + 29 < NH) ? (rn0 + 29) : NH;
    const bool do_readout = (tid < 7 * OD);

    // ---- xt loader mapping: thread i<120 loads feature i each step ----
    const float* xsrc = nullptr;
    int xoff = 0;
    if (tid < IND) {
        int c  = tid / 40;
        int dd = tid - c * 40;
        xsrc = x + ((size_t)(b * 3 + c) * TT) * 40 + dd;   // + t*40 per step
        xoff = (tid / PER) * 16 + (tid % PER);
    }

    // prologue: xs for t=0 into buffer 0
    if (tid < IND) xsbuf[0][xoff] = xsrc[0];
    __syncthreads();

    for (int t = 0; t < TT; t++) {
        const int cur = t & 1;

        // prefetch next step's input (latency hidden under dendrite compute)
        float xn = 0.0f;
        if (tid < IND && (t + 1) < TT) xn = xsrc[(size_t)(t + 1) * 40];

        // ---- dendrite + soma (threads 0..199) ----
        if (tid < NH) {
            const float4* xs4 = (const float4*)xsbuf[cur];
            float l = bb1;
            #pragma unroll
            for (int k = 0; k < BR; k++) {
                float4 a = xs4[k * 4 + 0];
                float4 q = xs4[k * 4 + 1];
                float4 c4 = xs4[k * 4 + 2];
                float4 e = xs4[k * 4 + 3];
                // two independent sub-chains for ILP; slot 15 has w=0
                float sA = a.x * w[k*16 + 0];
                float sB = a.y * w[k*16 + 1];
                sA = fmaf(a.z,  w[k*16 + 2],  sA);
                sB = fmaf(a.w,  w[k*16 + 3],  sB);
                sA = fmaf(q.x,  w[k*16 + 4],  sA);
                sB = fmaf(q.y,  w[k*16 + 5],  sB);
                sA = fmaf(q.z,  w[k*16 + 6],  sA);
                sB = fmaf(q.w,  w[k*16 + 7],  sB);
                sA = fmaf(c4.x, w[k*16 + 8],  sA);
                sB = fmaf(c4.y, w[k*16 + 9],  sB);
                sA = fmaf(c4.z, w[k*16 + 10], sA);
                sB = fmaf(c4.w, w[k*16 + 11], sB);
                sA = fmaf(e.x,  w[k*16 + 12], sA);
                sB = fmaf(e.y,  w[k*16 + 13], sB);
                sA = fmaf(e.z,  w[k*16 + 14], sA);
                float I = sA + sB;
                // d = beta*d + (1-beta)*I  ==  fma(beta, d-I, I)
                float dk = fmaf(beta[k], dstate[k] - I, I);
                dstate[k] = dk;
                l += dk;
            }
            // mem1 = a1*(mem1 - spk) + (1-a1)*l == fma(a1, (mem1-spk)-l, l)
            float m = fmaf(alpha1, (mem1 - spk) - l, l);
            mem1 = m;
            spk  = (m > 1.0f) ? 1.0f : 0.0f;
            spkS[tid] = spk;
        }
        __syncthreads();   // (C): spikes visible; xsbuf[cur] reads finished

        // stage next xt into the other buffer (consumed only after (D))
        if (tid < IND && (t + 1) < TT) xsbuf[cur ^ 1][xoff] = xn;

        // ---- readout partials: 245 threads, 35 outputs x 7 neuron slices ----
        if (do_readout) {
            const float* wrow = &W2s[o_slice * W2STRIDE];
            float p = 0.0f;
            for (int nn = rn0; nn < rn1; nn++)
                p = fmaf(spkS[nn], wrow[nn], p);
            psum[tid] = p;
        }
        __syncthreads();   // (D): psum + next xs visible

        // ---- reduce + leaky readout integrator (threads 0..34) ----
        if (tid < OD) {
            float r = bb2;
            #pragma unroll
            for (int s2 = 0; s2 < 7; s2++) r += psum[s2 * OD + tid];
            mem2 = fmaf(alpha2, mem2 - r, r);
            racc += mem2;
        }
    }

    // ---- epilogue: log_softmax(acc / T) over 35 logits ----
    if (tid < OD) accS[tid] = racc * (1.0f / TT);
    __syncthreads();
    if (tid < OD) {
        float m = -INFINITY;
        #pragma unroll
        for (int i = 0; i < OD; i++) m = fmaxf(m, accS[i]);
        float se = 0.0f;
        #pragma unroll
        for (int i = 0; i < OD; i++) se += expf(accS[i] - m);
        out[(size_t)b * OD + tid] = accS[tid] - m - logf(se);
    }
}

extern "C" void kernel_launch(void* const* d_in, const int* in_sizes, int n_in,
                              void* d_out, int out_size)
{
    const float* x      = (const float*)d_in[0];
    const float* W1     = (const float*)d_in[1];
    const float* b1     = (const float*)d_in[2];
    const float* tau_m1 = (const float*)d_in[3];
    const float* tau_n1 = (const float*)d_in[4];
    const float* W2     = (const float*)d_in[5];
    const float* b2     = (const float*)d_in[6];
    const float* tau_m2 = (const float*)d_in[7];
    float* out = (float*)d_out;

    const int B = in_sizes[0] / (3 * TT * 40);   // 512
    snn_fused_kernel<<<B, 256>>>(x, W1, b1, tau_m1, tau_n1, W2, b2, tau_m2, out);
}

// round 2
// speedup vs baseline: 1.5384x; 1.5384x over previous
#include <cuda_runtime.h>
#include <math.h>

#define NH   200
#define BR   8
#define IND  120
#define OD   35
#define TT   250
#define PER  15
#define BPC  4      // batches per CTA
#define W2S  201    // padded W2 row stride (conflict-free smem)

typedef unsigned long long u64;

__device__ __forceinline__ u64 pk2(float lo, float hi) {
    u64 r; asm("mov.b64 %0,{%1,%2};" : "=l"(r) : "f"(lo), "f"(hi)); return r;
}
__device__ __forceinline__ void upk2(u64 v, float& lo, float& hi) {
    asm("mov.b64 {%0,%1},%2;" : "=f"(lo), "=f"(hi) : "l"(v));
}
__device__ __forceinline__ u64 fma2(u64 a, u64 b, u64 c) {
    u64 d; asm("fma.rn.f32x2 %0,%1,%2,%3;" : "=l"(d) : "l"(a), "l"(b), "l"(c)); return d;
}
__device__ __forceinline__ u64 mul2(u64 a, u64 b) {
    u64 d; asm("mul.rn.f32x2 %0,%1,%2;" : "=l"(d) : "l"(a), "l"(b)); return d;
}
__device__ __forceinline__ u64 add2(u64 a, u64 b) {
    u64 d; asm("add.rn.f32x2 %0,%1,%2;" : "=l"(d) : "l"(a), "l"(b)); return d;
}
__device__ __forceinline__ float sigm(float v) { return 1.0f / (1.0f + expf(-v)); }

__global__ __launch_bounds__(256, 1)
void snn4_kernel(const float* __restrict__ x,
                 const float* __restrict__ W1,
                 const float* __restrict__ b1,
                 const float* __restrict__ tau_m1,
                 const float* __restrict__ tau_n1,
                 const float* __restrict__ W2,
                 const float* __restrict__ b2,
                 const float* __restrict__ tau_m2,
                 float* __restrict__ out)
{
    __shared__ __align__(16) float xs[2][BPC][128]; // double-buffered branch-padded inputs
    __shared__ u64  spkB[2][2][NH];                 // [buf][batch-pair][neuron] packed spikes
    __shared__ u64  psB[2][2][7 * OD];              // [buf][pair][slice*35+o] packed partials
    __shared__ float W2s[OD * W2S];
    __shared__ float accS[BPC][OD];

    const int tid = threadIdx.x;
    const int b0  = blockIdx.x * BPC;

    // ---- W2 -> smem (padded rows) ----
    for (int i = tid; i < OD * NH; i += 256) {
        int o = i / NH, n = i - o * NH;
        W2s[o * W2S + n] = W2[i];
    }
    // ---- zero slot-15 pads (2 bufs x 4 batches x 8 branches = 64) ----
    if (tid < 64) {
        int buf = tid >> 5, rest = tid & 31, bj = rest >> 3, k = rest & 7;
        xs[buf][bj][k * 16 + 15] = 0.0f;
    }

    // ---- per-neuron weights with (1-beta) folded in, slot-pair packed ----
    u64   w2[64];                 // 8 branches x 8 slot-pairs (slot15 pad = 0)
    float beta[BR], dst[BPC][BR];
    float a1 = 0.f, oma1 = 0.f, bb1 = 0.f, mem1[BPC], spkv[BPC];

    if (tid < NH) {
        #pragma unroll
        for (int k = 0; k < BR; k++) {
            float bt = sigm(tau_n1[tid * BR + k]);
            beta[k] = bt;
            float sc = 1.0f - bt;
            const float* src = W1 + (size_t)tid * (BR * IND) + k * IND + k * PER;
            float wr[16];
            #pragma unroll
            for (int j = 0; j < PER; j++) wr[j] = src[j] * sc;
            wr[15] = 0.0f;
            #pragma unroll
            for (int m = 0; m < 8; m++) w2[k * 8 + m] = pk2(wr[2 * m], wr[2 * m + 1]);
        }
        a1 = sigm(tau_m1[tid]); oma1 = 1.0f - a1; bb1 = b1[tid];
    }
    #pragma unroll
    for (int bj = 0; bj < BPC; bj++) {
        mem1[bj] = 0.f; spkv[bj] = 0.f;
        #pragma unroll
        for (int k = 0; k < BR; k++) dst[bj][k] = 0.f;
    }

    // ---- readout state ----
    float a2 = 0.f, bb2 = 0.f, mem2[BPC], racc[BPC];
    #pragma unroll
    for (int bj = 0; bj < BPC; bj++) { mem2[bj] = 0.f; racc[bj] = 0.f; }
    if (tid < OD) { a2 = sigm(tau_m2[tid]); bb2 = b2[tid]; }

    // readout slice mapping: tid = ss*35 + oo
    const int ss = tid / OD, oo = tid - ss * OD;
    const int rn0 = ss * 29;
    const int rn1 = (rn0 + 29 < NH) ? (rn0 + 29) : NH;
    const bool doP2 = (tid < 7 * OD);

    // loader mapping: thread i<120 loads feature i for all 4 batches
    const float* xsrc = nullptr;
    int xo = 0;
    if (tid < IND) {
        int c = tid / 40, dd = tid - c * 40;
        xsrc = x + ((size_t)(b0 * 3 + c) * TT) * 40 + dd;  // + bj*3*TT*40 + t*40
        xo = (tid / PER) * 16 + (tid % PER);
    }

    // prologue: x_0 -> buffer 0
    if (tid < IND) {
        #pragma unroll
        for (int bj = 0; bj < BPC; bj++)
            xs[0][bj][xo] = xsrc[(size_t)bj * 3 * TT * 40];
    }
    __syncthreads();

    // ======== main loop: 1 barrier/iteration, 3-stage software pipeline ========
    for (int t = 0; t < TT + 2; t++) {
        const int cur = t & 1, prv = cur ^ 1;

        // prefetch x_{t+1} (global latency hidden under dendrite compute)
        float xn[BPC];
        if (tid < IND && t < TT - 1) {
            #pragma unroll
            for (int bj = 0; bj < BPC; bj++)
                xn[bj] = xsrc[(size_t)bj * 3 * TT * 40 + (size_t)(t + 1) * 40];
        }

        // ---- stage 1: dendrite + soma for step t ----
        if (t < TT && tid < NH) {
            #pragma unroll
            for (int bj = 0; bj < BPC; bj++) {
                const ulonglong2* xv = (const ulonglong2*)xs[cur][bj];
                float l = bb1;
                #pragma unroll
                for (int k = 0; k < BR; k++) {
                    ulonglong2 v0 = xv[k * 4 + 0];
                    ulonglong2 v1 = xv[k * 4 + 1];
                    ulonglong2 v2 = xv[k * 4 + 2];
                    ulonglong2 v3 = xv[k * 4 + 3];
                    u64 sA = mul2(v0.x, w2[k * 8 + 0]);
                    u64 sB = mul2(v0.y, w2[k * 8 + 1]);
                    sA = fma2(v1.x, w2[k * 8 + 2], sA);
                    sB = fma2(v1.y, w2[k * 8 + 3], sB);
                    sA = fma2(v2.x, w2[k * 8 + 4], sA);
                    sB = fma2(v2.y, w2[k * 8 + 5], sB);
                    sA = fma2(v3.x, w2[k * 8 + 6], sA);
                    sB = fma2(v3.y, w2[k * 8 + 7], sB);
                    u64 I2 = add2(sA, sB);
                    float ilo, ihi; upk2(I2, ilo, ihi);
                    // weights pre-scaled by (1-beta):  d = beta*d + I'
                    float d = fmaf(beta[k], dst[bj][k], ilo + ihi);
                    dst[bj][k] = d;
                    l += d;
                }
                float u = mem1[bj] - spkv[bj];           // V_TH = 1
                float m = fmaf(a1, u, oma1 * l);
                mem1[bj] = m;
                spkv[bj] = (m > 1.0f) ? 1.0f : 0.0f;
            }
            spkB[cur][0][tid] = pk2(spkv[0], spkv[1]);
            spkB[cur][1][tid] = pk2(spkv[2], spkv[3]);
        }

        // stage next x into the other buffer
        if (tid < IND && t < TT - 1) {
            #pragma unroll
            for (int bj = 0; bj < BPC; bj++)
                xs[prv][bj][xo] = xn[bj];
        }

        // ---- stage 2: readout partials for step t-1 ----
        if (doP2 && t >= 1 && t <= TT) {
            u64 p0 = 0ULL, p1 = 0ULL;
            for (int nn = rn0; nn < rn1; nn++) {
                float wv = W2s[oo * W2S + nn];
                u64 wd = pk2(wv, wv);
                p0 = fma2(spkB[prv][0][nn], wd, p0);
                p1 = fma2(spkB[prv][1][nn], wd, p1);
            }
            psB[cur][0][tid] = p0;
            psB[cur][1][tid] = p1;
        }

        // ---- stage 3: reduce + leaky integrator for step t-2 ----
        if (tid < OD && t >= 2) {
            #pragma unroll
            for (int p = 0; p < 2; p++) {
                u64 r = psB[prv][p][tid];
                #pragma unroll
                for (int s2 = 1; s2 < 7; s2++)
                    r = add2(r, psB[prv][p][s2 * OD + tid]);
                float rl, rh; upk2(r, rl, rh);
                float tot0 = rl + bb2;
                float m0 = fmaf(a2, mem2[2 * p] - tot0, tot0);
                mem2[2 * p] = m0; racc[2 * p] += m0;
                float tot1 = rh + bb2;
                float m1 = fmaf(a2, mem2[2 * p + 1] - tot1, tot1);
                mem2[2 * p + 1] = m1; racc[2 * p + 1] += m1;
            }
        }

        __syncthreads();
    }

    // ---- epilogue: log_softmax(acc/T) per batch ----
    if (tid < OD) {
        #pragma unroll
        for (int bj = 0; bj < BPC; bj++)
            accS[bj][tid] = racc[bj] * (1.0f / TT);
    }
    __syncthreads();
    if (tid < BPC * OD) {
        int bj = tid / OD, o = tid - bj * OD;
        float m = -INFINITY;
        #pragma unroll
        for (int i = 0; i < OD; i++) m = fmaxf(m, accS[bj][i]);
        float se = 0.0f;
        #pragma unroll
        for (int i = 0; i < OD; i++) se += expf(accS[bj][i] - m);
        out[(size_t)(b0 + bj) * OD + o] = accS[bj][o] - m - logf(se);
    }
}

extern "C" void kernel_launch(void* const* d_in, const int* in_sizes, int n_in,
                              void* d_out, int out_size)
{
    const float* x      = (const float*)d_in[0];
    const float* W1     = (const float*)d_in[1];
    const float* b1     = (const float*)d_in[2];
    const float* tau_m1 = (const float*)d_in[3];
    const float* tau_n1 = (const float*)d_in[4];
    const float* W2     = (const float*)d_in[5];
    const float* b2     = (const float*)d_in[6];
    const float* tau_m2 = (const float*)d_in[7];
    float* out = (float*)d_out;

    const int B = in_sizes[0] / (3 * TT * 40);   // 512
    snn4_kernel<<<B / BPC, 256>>>(x, W1, b1, tau_m1, tau_n1, W2, b2, tau_m2, out);
}